// round 15
// baseline (speedup 1.0000x reference)
#include <cuda_runtime.h>
#include <cuda_fp16.h>
#include <cstdint>

typedef unsigned long long ull;

#define M_OUT   8192
#define N_BATCH 4096
#define K_IN    512
#define K_SEL   204
#define CAP     64
#define DELTA   0.022f
#define ZC      1.64485f
#define NB      24
#define ZSTEP   0.02f
#define ZHALF   0.24f

// GEMM tiling: CTA 128(m) x 256(n), warp 64x64, 8 warps (2x4), BK=64, 2-stage
#define TM 128
#define TN 256
#define BKK 64
#define NSTG (K_IN / BKK)     // 8
#define ROWB 144              // bytes per smem row: 128 data + 16 pad
#define A_STG (TM * ROWB)     // 18432
#define B_STG (TN * ROWB)     // 36864
#define B_BASE (2 * A_STG)
#define SMEM_GEMM (2 * (A_STG + B_STG))   // 110592 B

// ---------------------------------------------------------------------------
// scratch
// ---------------------------------------------------------------------------
__device__ __half    g_Lh[(size_t)M_OUT * N_BATCH];
__device__ __half    g_Wh[(size_t)M_OUT * K_IN];
__device__ __half    g_Xh[(size_t)N_BATCH * K_IN];
__device__ float     g_sig[M_OUT];
__device__ unsigned  g_bits[(size_t)M_OUT * 128];
__device__ int       g_r[M_OUT];
__device__ int       g_ucnt[M_OUT];
__device__ int       g_uidx[(size_t)M_OUT * CAP];
__device__ int       g_dummy;

// ---------------------------------------------------------------------------
// helpers
// ---------------------------------------------------------------------------
__device__ __forceinline__ uint32_t smem_u32(const void* p) {
    uint32_t a;
    asm("{ .reg .u64 t; cvta.to.shared.u64 t, %1; cvt.u32.u64 %0, t; }"
        : "=r"(a) : "l"(p));
    return a;
}
__device__ __forceinline__ void cpasync16(uint32_t dst, const void* src) {
    asm volatile("cp.async.cg.shared.global [%0], [%1], 16;"
                 :: "r"(dst), "l"(src) : "memory");
}
#define CP_COMMIT() asm volatile("cp.async.commit_group;" ::: "memory")
#define CP_WAIT(n)  asm volatile("cp.async.wait_group %0;" :: "n"(n) : "memory")

__device__ __forceinline__ void ldsm4(uint32_t addr, uint32_t* r) {
    asm volatile("ldmatrix.sync.aligned.m8n8.x4.shared.b16 {%0,%1,%2,%3}, [%4];"
                 : "=r"(r[0]), "=r"(r[1]), "=r"(r[2]), "=r"(r[3]) : "r"(addr));
}
__device__ __forceinline__ void mma16816(float* c, const uint32_t* a,
                                         const uint32_t* b) {
    asm volatile(
        "mma.sync.aligned.m16n8k16.row.col.f32.f16.f16.f32 "
        "{%0,%1,%2,%3}, {%4,%5,%6,%7}, {%8,%9}, {%0,%1,%2,%3};"
        : "+f"(c[0]), "+f"(c[1]), "+f"(c[2]), "+f"(c[3])
        : "r"(a[0]), "r"(a[1]), "r"(a[2]), "r"(a[3]), "r"(b[0]), "r"(b[1]));
}

// ---------------------------------------------------------------------------
// 0) dummy kernel (profiling-ordinal shim: captured slot = 4th launch)
// ---------------------------------------------------------------------------
__global__ void dummy_kernel() {
    if (threadIdx.x == 0) g_dummy = 1;
}

// ---------------------------------------------------------------------------
// 1) convert fp32 -> fp16 (block per row); W blocks also reduce sigma
// ---------------------------------------------------------------------------
__global__ __launch_bounds__(128) void prep_kernel(const float* __restrict__ W,
                                                   const float* __restrict__ X) {
    __shared__ float s_w2[4];
    const int bid = blockIdx.x;
    const int tid = threadIdx.x;

    if (bid < M_OUT) {
        const float4 v = ((const float4*)(W + (size_t)bid * K_IN))[tid];
        __half2* dst = (__half2*)(g_Wh + (size_t)bid * K_IN);
        dst[2 * tid]     = __floats2half2_rn(v.x, v.y);
        dst[2 * tid + 1] = __floats2half2_rn(v.z, v.w);
        float w2 = v.x * v.x + v.y * v.y + v.z * v.z + v.w * v.w;
#pragma unroll
        for (int off = 16; off; off >>= 1)
            w2 += __shfl_xor_sync(0xffffffffu, w2, off);
        if ((tid & 31) == 0) s_w2[tid >> 5] = w2;
        __syncthreads();
        if (tid == 0)
            g_sig[bid] = sqrtf(s_w2[0] + s_w2[1] + s_w2[2] + s_w2[3]);
    } else {
        const int r = bid - M_OUT;
        const float4 v = ((const float4*)(X + (size_t)r * K_IN))[tid];
        __half2* dst = (__half2*)(g_Xh + (size_t)r * K_IN);
        dst[2 * tid]     = __floats2half2_rn(v.x, v.y);
        dst[2 * tid + 1] = __floats2half2_rn(v.z, v.w);
    }
}

// ---------------------------------------------------------------------------
// 2) HMMA GEMM: CTA 128x256, warp 64x64, BK=64, 2-stage, 1 barrier/stage
// ---------------------------------------------------------------------------
__global__ __launch_bounds__(256) void gemm_kernel(const float* __restrict__ bias) {
    extern __shared__ __align__(16) char smem[];
    const uint32_t sb = smem_u32(smem);

    const int tid = threadIdx.x;
    const int w = tid >> 5, lane = tid & 31;
    const int wm = w >> 2, wn = w & 3;
    const int g = lane >> 2, tg = lane & 3;
    const int m0 = blockIdx.y * TM, n0 = blockIdx.x * TN;

    const int rbase = tid >> 3;
    const uint32_t dOffBase = (uint32_t)(rbase * ROWB + (tid & 7) * 16);
    const __half* aSrcBase = g_Wh + (size_t)(m0 + rbase) * K_IN + (tid & 7) * 8;
    const __half* bSrcBase = g_Xh + (size_t)(n0 + rbase) * K_IN + (tid & 7) * 8;

#define ISSUE(st) do {                                                     \
        const uint32_t _ab = sb + ((st) & 1) * A_STG + dOffBase;           \
        const __half* _as = aSrcBase + (st) * BKK;                         \
        cpasync16(_ab,                 _as);                               \
        cpasync16(_ab + 1 * 32 * ROWB, _as + 1 * 32 * K_IN);               \
        cpasync16(_ab + 2 * 32 * ROWB, _as + 2 * 32 * K_IN);               \
        cpasync16(_ab + 3 * 32 * ROWB, _as + 3 * 32 * K_IN);               \
        const uint32_t _bb = sb + B_BASE + ((st) & 1) * B_STG + dOffBase;  \
        const __half* _bs = bSrcBase + (st) * BKK;                         \
        cpasync16(_bb,                 _bs);                               \
        cpasync16(_bb + 1 * 32 * ROWB, _bs + 1 * 32 * K_IN);               \
        cpasync16(_bb + 2 * 32 * ROWB, _bs + 2 * 32 * K_IN);               \
        cpasync16(_bb + 3 * 32 * ROWB, _bs + 3 * 32 * K_IN);               \
        cpasync16(_bb + 4 * 32 * ROWB, _bs + 4 * 32 * K_IN);               \
        cpasync16(_bb + 5 * 32 * ROWB, _bs + 5 * 32 * K_IN);               \
        cpasync16(_bb + 6 * 32 * ROWB, _bs + 6 * 32 * K_IN);               \
        cpasync16(_bb + 7 * 32 * ROWB, _bs + 7 * 32 * K_IN);               \
        CP_COMMIT();                                                       \
    } while (0)

    ISSUE(0);

    float acc[4][8][4];
#pragma unroll
    for (int i = 0; i < 4; i++)
#pragma unroll
        for (int j = 0; j < 8; j++)
#pragma unroll
            for (int r = 0; r < 4; r++) acc[i][j][r] = 0.f;

    const uint32_t aLane =
        (uint32_t)(wm * 64 + (lane & 15)) * ROWB + (uint32_t)(lane >> 4) * 16;
    const uint32_t bLane =
        (uint32_t)(wn * 64 + ((lane >> 4) * 8) + (lane & 7)) * ROWB +
        (uint32_t)((lane >> 3) & 1) * 16;

    for (int s = 0; s < NSTG; s++) {
        CP_WAIT(0);
        __syncthreads();
        if (s + 1 < NSTG) ISSUE(s + 1);
        const int bufi = s & 1;
        const uint32_t aS = sb + bufi * A_STG + aLane;
        const uint32_t bS = sb + B_BASE + bufi * B_STG + bLane;
#pragma unroll
        for (int j = 0; j < 4; j++) {
            uint32_t a[4][4], b[8][2];
#pragma unroll
            for (int i = 0; i < 4; i++)
                ldsm4(aS + (uint32_t)(i * 16 * ROWB) + j * 32, a[i]);
#pragma unroll
            for (int jj = 0; jj < 4; jj++) {
                uint32_t r[4];
                ldsm4(bS + (uint32_t)(jj * 16 * ROWB) + j * 32, r);
                b[2 * jj][0] = r[0]; b[2 * jj][1] = r[1];
                b[2 * jj + 1][0] = r[2]; b[2 * jj + 1][1] = r[3];
            }
#pragma unroll
            for (int i = 0; i < 4; i++)
#pragma unroll
                for (int jn = 0; jn < 8; jn++) mma16816(acc[i][jn], a[i], b[jn]);
        }
    }
#undef ISSUE

#pragma unroll
    for (int i = 0; i < 4; i++) {
        const int o_lo = m0 + wm * 64 + i * 16 + g;
        const float b_lo = bias[o_lo];
        const float b_hi = bias[o_lo + 8];
#pragma unroll
        for (int jn = 0; jn < 8; jn++) {
            const int n = n0 + wn * 64 + jn * 8 + tg * 2;
            *(__half2*)(g_Lh + (size_t)o_lo * N_BATCH + n) =
                __floats2half2_rn(acc[i][jn][0] + b_lo, acc[i][jn][1] + b_lo);
            *(__half2*)(g_Lh + (size_t)(o_lo + 8) * N_BATCH + n) =
                __floats2half2_rn(acc[i][jn][2] + b_hi, acc[i][jn][3] + b_hi);
        }
    }
}

// ---------------------------------------------------------------------------
// 3) select: bucket-histogram + band classification + bitmask emission
// ---------------------------------------------------------------------------
__global__ __launch_bounds__(256) void select_kernel(const float* __restrict__ bias) {
    __shared__ int hist[NB];
    __shared__ int sTop, sA, scnt;
    __shared__ float sThi, sTlo;
    __shared__ int sBad;

    const int tid = threadIdx.x;
    const int o = blockIdx.x;

    if (tid < NB) hist[tid] = 0;
    if (tid == 0) { sTop = 0; sA = 0; scnt = 0; sBad = 0; }
    __syncthreads();

    const float sigma = g_sig[o];
    const float stepv = ZSTEP * sigma;
    const float t0 = bias[o] + (ZC - ZHALF) * sigma;
    const float invstep = 1.0f / stepv;

    const __half2* col = (const __half2*)(g_Lh + (size_t)o * N_BATCH);
    float v[16];
#pragma unroll
    for (int q = 0; q < 8; q++) {
        const float2 f = __half22float2(col[tid + 256 * q]);
        v[2 * q] = f.x;
        v[2 * q + 1] = f.y;
    }

    int top = 0;
#pragma unroll
    for (int q = 0; q < 16; q++) {
        const float f = (v[q] - t0) * invstep;
        if (f >= (float)NB) top++;
        else if (f >= 0.f) atomicAdd(&hist[(int)f], 1);
    }
    top = __reduce_add_sync(0xffffffffu, top);
    if ((tid & 31) == 0 && top) atomicAdd(&sTop, top);
    __syncthreads();

    if (tid == 0) {
        int run = sTop;
        int e = -1;
        if (run >= K_SEL) {
            sBad = 1;
        } else {
            for (int i = NB - 1; i >= 0; i--) {
                run += hist[i];
                if (run >= K_SEL) { e = i; break; }
            }
            if (e < 0) sBad = 1;
        }
        if (e >= 0) {
            sThi = t0 + (float)(e + 1) * stepv + DELTA * sigma;
            sTlo = t0 + (float)e * stepv - DELTA * sigma;
        }
    }
    __syncthreads();
    if (sBad) {
        if (tid == 0) g_ucnt[o] = CAP + 1;
        return;
    }
    const float T_hi = sThi, T_lo = sTlo;

    const int wrp = tid >> 5, lane = tid & 31;
    int a = 0;
#pragma unroll
    for (int p = 0; p < 8; p++) {
        const float x0 = v[2 * p], x1 = v[2 * p + 1];
        const unsigned ev = __ballot_sync(0xffffffffu, x0 > T_hi);
        const unsigned od = __ballot_sync(0xffffffffu, x1 > T_hi);
        if (lane == 0) {
            const int cid = 8 * p + wrp;
            g_bits[(size_t)o * 128 + 2 * cid]     = ev;
            g_bits[(size_t)o * 128 + 2 * cid + 1] = od;
        }
        if (x0 > T_hi) a++;
        else if (x0 > T_lo) {
            const int pp = atomicAdd(&scnt, 1);
            if (pp < CAP) g_uidx[(size_t)o * CAP + pp] = 2 * tid + 512 * p;
        }
        if (x1 > T_hi) a++;
        else if (x1 > T_lo) {
            const int pp = atomicAdd(&scnt, 1);
            if (pp < CAP) g_uidx[(size_t)o * CAP + pp] = 2 * tid + 512 * p + 1;
        }
    }
    a = __reduce_add_sync(0xffffffffu, a);
    if ((tid & 31) == 0 && a) atomicAdd(&sA, a);
    __syncthreads();
    if (tid == 0) {
        if (scnt > CAP) {
            g_ucnt[o] = CAP + 1;
        } else {
            g_ucnt[o] = scnt;
            g_r[o] = K_SEL - sA;
        }
    }
}

// ---------------------------------------------------------------------------
// 4) mask: expand bitmask -> fp32; 128(b) x 32(o) tiles, float4 stores
// ---------------------------------------------------------------------------
__global__ __launch_bounds__(256) void mask_kernel(float* __restrict__ out) {
    __shared__ unsigned sbits[32][4];
    const int tx = threadIdx.x, ty = threadIdx.y;
    const int tid = ty * 32 + tx;
    const int b0 = blockIdx.x * 128, o0 = blockIdx.y * 32;

    if (tid < 128) {
        const int ol = tid >> 2, wi = tid & 3;
        sbits[ol][wi] = g_bits[(size_t)(o0 + ol) * 128 + (b0 >> 6) * 2 + wi];
    }
    __syncthreads();

    const int j = tx & 7;
    const int bg = tx >> 3;
#pragma unroll
    for (int i = 0; i < 4; i++) {
        const int b = ty * 16 + i * 4 + bg;
        const int c = b >> 6;
        const int idx = b & 63;
        const int sh = idx >> 1;
        const int par = idx & 1;
        float4 v;
#pragma unroll
        for (int k = 0; k < 4; k++) {
            const unsigned word = sbits[4 * j + k][2 * c + par];
            ((float*)&v)[k] = ((word >> sh) & 1u) ? 1.0f : 0.0f;
        }
        *(float4*)(out + (size_t)(b0 + b) * M_OUT + o0 + 4 * j) = v;
    }
}

// ---------------------------------------------------------------------------
// 5) repair: exact fp32 ascending-k chain; parallel rank selection
// ---------------------------------------------------------------------------
__global__ __launch_bounds__(128) void repair_kernel(const float* __restrict__ W,
                                                     const float* __restrict__ X,
                                                     const float* __restrict__ bias,
                                                     float* __restrict__ out) {
    const int o = blockIdx.x;
    const int tid = threadIdx.x;
    const int c = g_ucnt[o];
    if (c == 0) return;

    const float4* wr4 = (const float4*)(W + (size_t)o * K_IN);

    if (c <= CAP) {
        __shared__ float vals[CAP];
        __shared__ int idxs[CAP];
        if (tid < c) {
            const int b = g_uidx[(size_t)o * CAP + tid];
            const float4* xr4 = (const float4*)(X + (size_t)b * K_IN);
            float acc = 0.f;
            for (int k = 0; k < K_IN / 4; k++) {
                const float4 wv = wr4[k], xv = xr4[k];
                acc = __fmaf_rn(wv.x, xv.x, acc);
                acc = __fmaf_rn(wv.y, xv.y, acc);
                acc = __fmaf_rn(wv.z, xv.z, acc);
                acc = __fmaf_rn(wv.w, xv.w, acc);
            }
            vals[tid] = acc + bias[o];
            idxs[tid] = b;
        }
        __syncthreads();
        if (tid < c) {
            const int r = g_r[o];
            const float v = vals[tid];
            const int ib = idxs[tid];
            int rank = 0;
            for (int jj = 0; jj < c; jj++) {
                const float vj = vals[jj];
                rank += (vj > v || (vj == v && idxs[jj] < ib)) ? 1 : 0;
            }
            if (rank < r) out[(size_t)ib * M_OUT + o] = 1.0f;
        }
        return;
    }

    // fallback: recompute whole column exactly + exact radix select with ties
    __shared__ unsigned keys[N_BATCH];
    __shared__ unsigned hist[256];
    __shared__ unsigned s_prefix;
    __shared__ int s_rem, s_cut;
    for (int b = tid; b < N_BATCH; b += 128) {
        const float4* xr4 = (const float4*)(X + (size_t)b * K_IN);
        float acc = 0.f;
        for (int k = 0; k < K_IN / 4; k++) {
            const float4 wv = wr4[k], xv = xr4[k];
            acc = __fmaf_rn(wv.x, xv.x, acc);
            acc = __fmaf_rn(wv.y, xv.y, acc);
            acc = __fmaf_rn(wv.z, xv.z, acc);
            acc = __fmaf_rn(wv.w, xv.w, acc);
        }
        const float f = acc + bias[o];
        const unsigned u = __float_as_uint(f);
        keys[b] = u ^ ((u & 0x80000000u) ? 0xFFFFFFFFu : 0x80000000u);
    }
    if (tid == 0) { s_prefix = 0u; s_rem = K_SEL; }
    const unsigned himasks[4] = {0u, 0xFF000000u, 0xFFFF0000u, 0xFFFFFF00u};
#pragma unroll
    for (int pass = 0; pass < 4; pass++) {
        const int shift = 24 - 8 * pass;
        __syncthreads();
        hist[tid] = 0;
        hist[tid + 128] = 0;
        __syncthreads();
        const unsigned hm = himasks[pass];
        const unsigned pfx = s_prefix;
        for (int i = tid; i < N_BATCH; i += 128) {
            const unsigned u = keys[i];
            if ((u & hm) == (pfx & hm)) atomicAdd(&hist[(u >> shift) & 255], 1u);
        }
        __syncthreads();
        if (tid == 0) {
            unsigned cum = 0;
            int d;
            for (d = 255; d >= 0; d--) {
                cum += hist[d];
                if ((int)cum >= s_rem) break;
            }
            s_rem -= (int)(cum - hist[d]);
            s_prefix = pfx | ((unsigned)d << shift);
        }
    }
    __syncthreads();
    const unsigned tau = s_prefix;
    const int rem = s_rem;
    const int base = tid * 32;
    int cnt = 0;
#pragma unroll
    for (int j = 0; j < 32; j++) cnt += (keys[base + j] == tau) ? 1 : 0;
    __syncthreads();
    hist[tid] = (unsigned)cnt;
    __syncthreads();
    for (int off = 1; off < 128; off <<= 1) {
        const unsigned v = hist[tid];
        const unsigned a = (tid >= off) ? hist[tid - off] : 0u;
        __syncthreads();
        hist[tid] = v + a;
        __syncthreads();
    }
    const int incl = (int)hist[tid];
    const int excl = incl - cnt;
    if (excl < rem && rem <= incl) {
        int need = rem - excl;
        for (int j = 0; j < 32; j++) {
            if (keys[base + j] == tau && --need == 0) { s_cut = base + j; break; }
        }
    }
    __syncthreads();
    const int cut = s_cut;
    for (int b = tid; b < N_BATCH; b += 128) {
        const unsigned k = keys[b];
        out[(size_t)b * M_OUT + o] = (k > tau || (k == tau && b <= cut)) ? 1.0f : 0.0f;
    }
}

// ---------------------------------------------------------------------------
extern "C" void kernel_launch(void* const* d_in, const int* in_sizes, int n_in,
                              void* d_out, int out_size) {
    const float* x = (const float*)d_in[0];  // [4096, 512]
    const float* W = (const float*)d_in[1];  // [8192, 512]
    const float* b = (const float*)d_in[2];  // [8192]
    float* out = (float*)d_out;              // [4096, 8192]

    cudaFuncSetAttribute(gemm_kernel,
                         cudaFuncAttributeMaxDynamicSharedMemorySize, SMEM_GEMM);

    prep_kernel<<<M_OUT + N_BATCH, 128>>>(W, x);
    dummy_kernel<<<1, 32>>>();
    gemm_kernel<<<dim3(N_BATCH / TN, M_OUT / TM), 256, SMEM_GEMM>>>(b);
    select_kernel<<<M_OUT, 256>>>(b);      // <- 4th launch: captured by ncu
    mask_kernel<<<dim3(N_BATCH / 128, M_OUT / 32), dim3(32, 8)>>>(out);
    repair_kernel<<<M_OUT, 128>>>(W, x, b, out);
}

// round 16
// speedup vs baseline: 1.0262x; 1.0262x over previous
#include <cuda_runtime.h>
#include <cuda_fp16.h>
#include <cstdint>

typedef unsigned long long ull;

#define M_OUT   8192
#define N_BATCH 4096
#define K_IN    512
#define K_SEL   204
#define CAP     64
#define DELTA   0.022f
#define ZC      1.64485f
#define NB      24
#define ZSTEP   0.02f
#define ZHALF   0.24f

// GEMM tiling: CTA 128(m) x 128(n), warp 64x32, 8 warps (2x4), BK=64, 2-stage
// smem 72 KB -> 2 CTAs/SM -> 4 warps/SMSP
#define TM 128
#define TN 128
#define BKK 64
#define NSTG (K_IN / BKK)     // 8
#define ROWB 144              // bytes per smem row: 128 data + 16 pad
#define A_STG (TM * ROWB)     // 18432
#define B_STG (TN * ROWB)     // 18432
#define B_BASE (2 * A_STG)
#define SMEM_GEMM (2 * (A_STG + B_STG))   // 73728 B

// ---------------------------------------------------------------------------
// scratch
// ---------------------------------------------------------------------------
__device__ __half    g_Lh[(size_t)M_OUT * N_BATCH];
__device__ __half    g_Wh[(size_t)M_OUT * K_IN];
__device__ __half    g_Xh[(size_t)N_BATCH * K_IN];
__device__ float     g_sig[M_OUT];
__device__ unsigned  g_bits[(size_t)M_OUT * 128];
__device__ int       g_r[M_OUT];
__device__ int       g_ucnt[M_OUT];
__device__ int       g_uidx[(size_t)M_OUT * CAP];
__device__ int       g_dummy;

// ---------------------------------------------------------------------------
// helpers
// ---------------------------------------------------------------------------
__device__ __forceinline__ uint32_t smem_u32(const void* p) {
    uint32_t a;
    asm("{ .reg .u64 t; cvta.to.shared.u64 t, %1; cvt.u32.u64 %0, t; }"
        : "=r"(a) : "l"(p));
    return a;
}
__device__ __forceinline__ void cpasync16(uint32_t dst, const void* src) {
    asm volatile("cp.async.cg.shared.global [%0], [%1], 16;"
                 :: "r"(dst), "l"(src) : "memory");
}
#define CP_COMMIT() asm volatile("cp.async.commit_group;" ::: "memory")
#define CP_WAIT(n)  asm volatile("cp.async.wait_group %0;" :: "n"(n) : "memory")

__device__ __forceinline__ void ldsm4(uint32_t addr, uint32_t* r) {
    asm volatile("ldmatrix.sync.aligned.m8n8.x4.shared.b16 {%0,%1,%2,%3}, [%4];"
                 : "=r"(r[0]), "=r"(r[1]), "=r"(r[2]), "=r"(r[3]) : "r"(addr));
}
__device__ __forceinline__ void mma16816(float* c, const uint32_t* a,
                                         const uint32_t* b) {
    asm volatile(
        "mma.sync.aligned.m16n8k16.row.col.f32.f16.f16.f32 "
        "{%0,%1,%2,%3}, {%4,%5,%6,%7}, {%8,%9}, {%0,%1,%2,%3};"
        : "+f"(c[0]), "+f"(c[1]), "+f"(c[2]), "+f"(c[3])
        : "r"(a[0]), "r"(a[1]), "r"(a[2]), "r"(a[3]), "r"(b[0]), "r"(b[1]));
}

// ---------------------------------------------------------------------------
// 0) dummy kernel (profiling-ordinal shim: captured slot = 4th launch = gemm)
// ---------------------------------------------------------------------------
__global__ void dummy_kernel() {
    if (threadIdx.x == 0) g_dummy = 1;
}

// ---------------------------------------------------------------------------
// 1) convert fp32 -> fp16 (block per row); W blocks also reduce sigma
// ---------------------------------------------------------------------------
__global__ __launch_bounds__(128) void prep_kernel(const float* __restrict__ W,
                                                   const float* __restrict__ X) {
    __shared__ float s_w2[4];
    const int bid = blockIdx.x;
    const int tid = threadIdx.x;

    if (bid < M_OUT) {
        const float4 v = ((const float4*)(W + (size_t)bid * K_IN))[tid];
        __half2* dst = (__half2*)(g_Wh + (size_t)bid * K_IN);
        dst[2 * tid]     = __floats2half2_rn(v.x, v.y);
        dst[2 * tid + 1] = __floats2half2_rn(v.z, v.w);
        float w2 = v.x * v.x + v.y * v.y + v.z * v.z + v.w * v.w;
#pragma unroll
        for (int off = 16; off; off >>= 1)
            w2 += __shfl_xor_sync(0xffffffffu, w2, off);
        if ((tid & 31) == 0) s_w2[tid >> 5] = w2;
        __syncthreads();
        if (tid == 0)
            g_sig[bid] = sqrtf(s_w2[0] + s_w2[1] + s_w2[2] + s_w2[3]);
    } else {
        const int r = bid - M_OUT;
        const float4 v = ((const float4*)(X + (size_t)r * K_IN))[tid];
        __half2* dst = (__half2*)(g_Xh + (size_t)r * K_IN);
        dst[2 * tid]     = __floats2half2_rn(v.x, v.y);
        dst[2 * tid + 1] = __floats2half2_rn(v.z, v.w);
    }
}

// ---------------------------------------------------------------------------
// 2) HMMA GEMM: CTA 128x128, warp 64x32, BK=64, 2-stage, 2 CTAs/SM
// ---------------------------------------------------------------------------
__global__ __launch_bounds__(256, 2) void gemm_kernel(const float* __restrict__ bias) {
    extern __shared__ __align__(16) char smem[];
    const uint32_t sb = smem_u32(smem);

    const int tid = threadIdx.x;
    const int w = tid >> 5, lane = tid & 31;
    const int wm = w >> 2, wn = w & 3;            // warp grid 2(m) x 4(n)
    const int g = lane >> 2, tg = lane & 3;
    const int m0 = blockIdx.y * TM, n0 = blockIdx.x * TN;

    // copy plan: rows (tid>>3) + 32i, chunk col tid&7; 4 chunks per matrix
    const int rbase = tid >> 3;
    const uint32_t dOffBase = (uint32_t)(rbase * ROWB + (tid & 7) * 16);
    const __half* aSrcBase = g_Wh + (size_t)(m0 + rbase) * K_IN + (tid & 7) * 8;
    const __half* bSrcBase = g_Xh + (size_t)(n0 + rbase) * K_IN + (tid & 7) * 8;

#define ISSUE(st) do {                                                     \
        const uint32_t _ab = sb + ((st) & 1) * A_STG + dOffBase;           \
        const __half* _as = aSrcBase + (st) * BKK;                         \
        cpasync16(_ab,                 _as);                               \
        cpasync16(_ab + 1 * 32 * ROWB, _as + 1 * 32 * K_IN);               \
        cpasync16(_ab + 2 * 32 * ROWB, _as + 2 * 32 * K_IN);               \
        cpasync16(_ab + 3 * 32 * ROWB, _as + 3 * 32 * K_IN);               \
        const uint32_t _bb = sb + B_BASE + ((st) & 1) * B_STG + dOffBase;  \
        const __half* _bs = bSrcBase + (st) * BKK;                         \
        cpasync16(_bb,                 _bs);                               \
        cpasync16(_bb + 1 * 32 * ROWB, _bs + 1 * 32 * K_IN);               \
        cpasync16(_bb + 2 * 32 * ROWB, _bs + 2 * 32 * K_IN);               \
        cpasync16(_bb + 3 * 32 * ROWB, _bs + 3 * 32 * K_IN);               \
        CP_COMMIT();                                                       \
    } while (0)

    ISSUE(0);

    float acc[4][4][4];
#pragma unroll
    for (int i = 0; i < 4; i++)
#pragma unroll
        for (int j = 0; j < 4; j++)
#pragma unroll
            for (int r = 0; r < 4; r++) acc[i][j][r] = 0.f;

    const uint32_t aLane =
        (uint32_t)(wm * 64 + (lane & 15)) * ROWB + (uint32_t)(lane >> 4) * 16;
    const uint32_t bLane =
        (uint32_t)(wn * 32 + ((lane >> 4) * 8) + (lane & 7)) * ROWB +
        (uint32_t)((lane >> 3) & 1) * 16;

    for (int s = 0; s < NSTG; s++) {
        CP_WAIT(0);
        __syncthreads();
        if (s + 1 < NSTG) ISSUE(s + 1);
        const int bufi = s & 1;
        const uint32_t aS = sb + bufi * A_STG + aLane;
        const uint32_t bS = sb + B_BASE + bufi * B_STG + bLane;
#pragma unroll
        for (int j = 0; j < 4; j++) {     // four k16 steps per stage
            uint32_t a[4][4], b[4][2];
#pragma unroll
            for (int i = 0; i < 4; i++)
                ldsm4(aS + (uint32_t)(i * 16 * ROWB) + j * 32, a[i]);
#pragma unroll
            for (int jj = 0; jj < 2; jj++) {
                uint32_t r[4];
                ldsm4(bS + (uint32_t)(jj * 16 * ROWB) + j * 32, r);
                b[2 * jj][0] = r[0]; b[2 * jj][1] = r[1];
                b[2 * jj + 1][0] = r[2]; b[2 * jj + 1][1] = r[3];
            }
#pragma unroll
            for (int i = 0; i < 4; i++)
#pragma unroll
                for (int jn = 0; jn < 4; jn++) mma16816(acc[i][jn], a[i], b[jn]);
        }
    }
#undef ISSUE

#pragma unroll
    for (int i = 0; i < 4; i++) {
        const int o_lo = m0 + wm * 64 + i * 16 + g;
        const float b_lo = bias[o_lo];
        const float b_hi = bias[o_lo + 8];
#pragma unroll
        for (int jn = 0; jn < 4; jn++) {
            const int n = n0 + wn * 32 + jn * 8 + tg * 2;
            *(__half2*)(g_Lh + (size_t)o_lo * N_BATCH + n) =
                __floats2half2_rn(acc[i][jn][0] + b_lo, acc[i][jn][1] + b_lo);
            *(__half2*)(g_Lh + (size_t)(o_lo + 8) * N_BATCH + n) =
                __floats2half2_rn(acc[i][jn][2] + b_hi, acc[i][jn][3] + b_hi);
        }
    }
}

// ---------------------------------------------------------------------------
// 3) select: bucket-histogram + band classification + bitmask emission
// ---------------------------------------------------------------------------
__global__ __launch_bounds__(256) void select_kernel(const float* __restrict__ bias) {
    __shared__ int hist[NB];
    __shared__ int sTop, sA, scnt;
    __shared__ float sThi, sTlo;
    __shared__ int sBad;

    const int tid = threadIdx.x;
    const int o = blockIdx.x;

    if (tid < NB) hist[tid] = 0;
    if (tid == 0) { sTop = 0; sA = 0; scnt = 0; sBad = 0; }
    __syncthreads();

    const float sigma = g_sig[o];
    const float stepv = ZSTEP * sigma;
    const float t0 = bias[o] + (ZC - ZHALF) * sigma;
    const float invstep = 1.0f / stepv;

    const __half2* col = (const __half2*)(g_Lh + (size_t)o * N_BATCH);
    float v[16];
#pragma unroll
    for (int q = 0; q < 8; q++) {
        const float2 f = __half22float2(col[tid + 256 * q]);
        v[2 * q] = f.x;
        v[2 * q + 1] = f.y;
    }

    int top = 0;
#pragma unroll
    for (int q = 0; q < 16; q++) {
        const float f = (v[q] - t0) * invstep;
        if (f >= (float)NB) top++;
        else if (f >= 0.f) atomicAdd(&hist[(int)f], 1);
    }
    top = __reduce_add_sync(0xffffffffu, top);
    if ((tid & 31) == 0 && top) atomicAdd(&sTop, top);
    __syncthreads();

    if (tid == 0) {
        int run = sTop;
        int e = -1;
        if (run >= K_SEL) {
            sBad = 1;
        } else {
            for (int i = NB - 1; i >= 0; i--) {
                run += hist[i];
                if (run >= K_SEL) { e = i; break; }
            }
            if (e < 0) sBad = 1;
        }
        if (e >= 0) {
            sThi = t0 + (float)(e + 1) * stepv + DELTA * sigma;
            sTlo = t0 + (float)e * stepv - DELTA * sigma;
        }
    }
    __syncthreads();
    if (sBad) {
        if (tid == 0) g_ucnt[o] = CAP + 1;
        return;
    }
    const float T_hi = sThi, T_lo = sTlo;

    const int wrp = tid >> 5, lane = tid & 31;
    int a = 0;
#pragma unroll
    for (int p = 0; p < 8; p++) {
        const float x0 = v[2 * p], x1 = v[2 * p + 1];
        const unsigned ev = __ballot_sync(0xffffffffu, x0 > T_hi);
        const unsigned od = __ballot_sync(0xffffffffu, x1 > T_hi);
        if (lane == 0) {
            const int cid = 8 * p + wrp;
            g_bits[(size_t)o * 128 + 2 * cid]     = ev;
            g_bits[(size_t)o * 128 + 2 * cid + 1] = od;
        }
        if (x0 > T_hi) a++;
        else if (x0 > T_lo) {
            const int pp = atomicAdd(&scnt, 1);
            if (pp < CAP) g_uidx[(size_t)o * CAP + pp] = 2 * tid + 512 * p;
        }
        if (x1 > T_hi) a++;
        else if (x1 > T_lo) {
            const int pp = atomicAdd(&scnt, 1);
            if (pp < CAP) g_uidx[(size_t)o * CAP + pp] = 2 * tid + 512 * p + 1;
        }
    }
    a = __reduce_add_sync(0xffffffffu, a);
    if ((tid & 31) == 0 && a) atomicAdd(&sA, a);
    __syncthreads();
    if (tid == 0) {
        if (scnt > CAP) {
            g_ucnt[o] = CAP + 1;
        } else {
            g_ucnt[o] = scnt;
            g_r[o] = K_SEL - sA;
        }
    }
}

// ---------------------------------------------------------------------------
// 4) mask: expand bitmask -> fp32; 128(b) x 32(o) tiles, float4 stores
// ---------------------------------------------------------------------------
__global__ __launch_bounds__(256) void mask_kernel(float* __restrict__ out) {
    __shared__ unsigned sbits[32][4];
    const int tx = threadIdx.x, ty = threadIdx.y;
    const int tid = ty * 32 + tx;
    const int b0 = blockIdx.x * 128, o0 = blockIdx.y * 32;

    if (tid < 128) {
        const int ol = tid >> 2, wi = tid & 3;
        sbits[ol][wi] = g_bits[(size_t)(o0 + ol) * 128 + (b0 >> 6) * 2 + wi];
    }
    __syncthreads();

    const int j = tx & 7;
    const int bg = tx >> 3;
#pragma unroll
    for (int i = 0; i < 4; i++) {
        const int b = ty * 16 + i * 4 + bg;
        const int c = b >> 6;
        const int idx = b & 63;
        const int sh = idx >> 1;
        const int par = idx & 1;
        float4 v;
#pragma unroll
        for (int k = 0; k < 4; k++) {
            const unsigned word = sbits[4 * j + k][2 * c + par];
            ((float*)&v)[k] = ((word >> sh) & 1u) ? 1.0f : 0.0f;
        }
        *(float4*)(out + (size_t)(b0 + b) * M_OUT + o0 + 4 * j) = v;
    }
}

// ---------------------------------------------------------------------------
// 5) repair: exact fp32 ascending-k chain; parallel rank selection
// ---------------------------------------------------------------------------
__global__ __launch_bounds__(128) void repair_kernel(const float* __restrict__ W,
                                                     const float* __restrict__ X,
                                                     const float* __restrict__ bias,
                                                     float* __restrict__ out) {
    const int o = blockIdx.x;
    const int tid = threadIdx.x;
    const int c = g_ucnt[o];
    if (c == 0) return;

    const float4* wr4 = (const float4*)(W + (size_t)o * K_IN);

    if (c <= CAP) {
        __shared__ float vals[CAP];
        __shared__ int idxs[CAP];
        if (tid < c) {
            const int b = g_uidx[(size_t)o * CAP + tid];
            const float4* xr4 = (const float4*)(X + (size_t)b * K_IN);
            float acc = 0.f;
            for (int k = 0; k < K_IN / 4; k++) {
                const float4 wv = wr4[k], xv = xr4[k];
                acc = __fmaf_rn(wv.x, xv.x, acc);
                acc = __fmaf_rn(wv.y, xv.y, acc);
                acc = __fmaf_rn(wv.z, xv.z, acc);
                acc = __fmaf_rn(wv.w, xv.w, acc);
            }
            vals[tid] = acc + bias[o];
            idxs[tid] = b;
        }
        __syncthreads();
        if (tid < c) {
            const int r = g_r[o];
            const float v = vals[tid];
            const int ib = idxs[tid];
            int rank = 0;
            for (int jj = 0; jj < c; jj++) {
                const float vj = vals[jj];
                rank += (vj > v || (vj == v && idxs[jj] < ib)) ? 1 : 0;
            }
            if (rank < r) out[(size_t)ib * M_OUT + o] = 1.0f;
        }
        return;
    }

    // fallback: recompute whole column exactly + exact radix select with ties
    __shared__ unsigned keys[N_BATCH];
    __shared__ unsigned hist[256];
    __shared__ unsigned s_prefix;
    __shared__ int s_rem, s_cut;
    for (int b = tid; b < N_BATCH; b += 128) {
        const float4* xr4 = (const float4*)(X + (size_t)b * K_IN);
        float acc = 0.f;
        for (int k = 0; k < K_IN / 4; k++) {
            const float4 wv = wr4[k], xv = xr4[k];
            acc = __fmaf_rn(wv.x, xv.x, acc);
            acc = __fmaf_rn(wv.y, xv.y, acc);
            acc = __fmaf_rn(wv.z, xv.z, acc);
            acc = __fmaf_rn(wv.w, xv.w, acc);
        }
        const float f = acc + bias[o];
        const unsigned u = __float_as_uint(f);
        keys[b] = u ^ ((u & 0x80000000u) ? 0xFFFFFFFFu : 0x80000000u);
    }
    if (tid == 0) { s_prefix = 0u; s_rem = K_SEL; }
    const unsigned himasks[4] = {0u, 0xFF000000u, 0xFFFF0000u, 0xFFFFFF00u};
#pragma unroll
    for (int pass = 0; pass < 4; pass++) {
        const int shift = 24 - 8 * pass;
        __syncthreads();
        hist[tid] = 0;
        hist[tid + 128] = 0;
        __syncthreads();
        const unsigned hm = himasks[pass];
        const unsigned pfx = s_prefix;
        for (int i = tid; i < N_BATCH; i += 128) {
            const unsigned u = keys[i];
            if ((u & hm) == (pfx & hm)) atomicAdd(&hist[(u >> shift) & 255], 1u);
        }
        __syncthreads();
        if (tid == 0) {
            unsigned cum = 0;
            int d;
            for (d = 255; d >= 0; d--) {
                cum += hist[d];
                if ((int)cum >= s_rem) break;
            }
            s_rem -= (int)(cum - hist[d]);
            s_prefix = pfx | ((unsigned)d << shift);
        }
    }
    __syncthreads();
    const unsigned tau = s_prefix;
    const int rem = s_rem;
    const int base = tid * 32;
    int cnt = 0;
#pragma unroll
    for (int j = 0; j < 32; j++) cnt += (keys[base + j] == tau) ? 1 : 0;
    __syncthreads();
    hist[tid] = (unsigned)cnt;
    __syncthreads();
    for (int off = 1; off < 128; off <<= 1) {
        const unsigned v = hist[tid];
        const unsigned a = (tid >= off) ? hist[tid - off] : 0u;
        __syncthreads();
        hist[tid] = v + a;
        __syncthreads();
    }
    const int incl = (int)hist[tid];
    const int excl = incl - cnt;
    if (excl < rem && rem <= incl) {
        int need = rem - excl;
        for (int j = 0; j < 32; j++) {
            if (keys[base + j] == tau && --need == 0) { s_cut = base + j; break; }
        }
    }
    __syncthreads();
    const int cut = s_cut;
    for (int b = tid; b < N_BATCH; b += 128) {
        const unsigned k = keys[b];
        out[(size_t)b * M_OUT + o] = (k > tau || (k == tau && b <= cut)) ? 1.0f : 0.0f;
    }
}

// ---------------------------------------------------------------------------
extern "C" void kernel_launch(void* const* d_in, const int* in_sizes, int n_in,
                              void* d_out, int out_size) {
    const float* x = (const float*)d_in[0];  // [4096, 512]
    const float* W = (const float*)d_in[1];  // [8192, 512]
    const float* b = (const float*)d_in[2];  // [8192]
    float* out = (float*)d_out;              // [4096, 8192]

    cudaFuncSetAttribute(gemm_kernel,
                         cudaFuncAttributeMaxDynamicSharedMemorySize, SMEM_GEMM);

    prep_kernel<<<M_OUT + N_BATCH, 128>>>(W, x);
    dummy_kernel<<<1, 32>>>();
    dummy_kernel<<<1, 32>>>();
    gemm_kernel<<<dim3(N_BATCH / TN, M_OUT / TM), 256, SMEM_GEMM>>>(b);  // 4th: profiled
    select_kernel<<<M_OUT, 256>>>(b);
    mask_kernel<<<dim3(N_BATCH / 128, M_OUT / 32), dim3(32, 8)>>>(out);
    repair_kernel<<<M_OUT, 128>>>(W, x, b, out);
}

// round 17
// speedup vs baseline: 1.0468x; 1.0201x over previous
#include <cuda_runtime.h>
#include <cuda_fp16.h>
#include <cstdint>

typedef unsigned long long ull;

#define M_OUT   8192
#define N_BATCH 4096
#define K_IN    512
#define K_SEL   204
#define CAP     64
#define DELTA   0.022f
#define ZC      1.64485f
#define NB      24
#define ZSTEP   0.02f
#define ZHALF   0.24f

// GEMM tiling: CTA 128(m) x 128(n), warp 64x32, 8 warps (2x4), BK=64, 2-stage
// smem 72 KB -> 2 CTAs/SM -> 4 warps/SMSP
#define TM 128
#define TN 128
#define BKK 64
#define NSTG (K_IN / BKK)     // 8
#define ROWB 144              // bytes per smem row: 128 data + 16 pad
#define A_STG (TM * ROWB)     // 18432
#define B_STG (TN * ROWB)     // 18432
#define B_BASE (2 * A_STG)
#define SMEM_GEMM (2 * (A_STG + B_STG))   // 73728 B

// ---------------------------------------------------------------------------
// scratch
// ---------------------------------------------------------------------------
__device__ __half    g_Lh[(size_t)M_OUT * N_BATCH];
__device__ __half    g_Wh[(size_t)M_OUT * K_IN];
__device__ __half    g_Xh[(size_t)N_BATCH * K_IN];
__device__ float     g_sig[M_OUT];
__device__ unsigned  g_bits[(size_t)M_OUT * 128];
__device__ int       g_r[M_OUT];
__device__ int       g_ucnt[M_OUT];
__device__ int       g_uidx[(size_t)M_OUT * CAP];

// ---------------------------------------------------------------------------
// helpers
// ---------------------------------------------------------------------------
__device__ __forceinline__ uint32_t smem_u32(const void* p) {
    uint32_t a;
    asm("{ .reg .u64 t; cvta.to.shared.u64 t, %1; cvt.u32.u64 %0, t; }"
        : "=r"(a) : "l"(p));
    return a;
}
__device__ __forceinline__ void cpasync16(uint32_t dst, const void* src) {
    asm volatile("cp.async.cg.shared.global [%0], [%1], 16;"
                 :: "r"(dst), "l"(src) : "memory");
}
#define CP_COMMIT() asm volatile("cp.async.commit_group;" ::: "memory")
#define CP_WAIT(n)  asm volatile("cp.async.wait_group %0;" :: "n"(n) : "memory")

__device__ __forceinline__ void ldsm4(uint32_t addr, uint32_t* r) {
    asm volatile("ldmatrix.sync.aligned.m8n8.x4.shared.b16 {%0,%1,%2,%3}, [%4];"
                 : "=r"(r[0]), "=r"(r[1]), "=r"(r[2]), "=r"(r[3]) : "r"(addr));
}
__device__ __forceinline__ void mma16816(float* c, const uint32_t* a,
                                         const uint32_t* b) {
    asm volatile(
        "mma.sync.aligned.m16n8k16.row.col.f32.f16.f16.f32 "
        "{%0,%1,%2,%3}, {%4,%5,%6,%7}, {%8,%9}, {%0,%1,%2,%3};"
        : "+f"(c[0]), "+f"(c[1]), "+f"(c[2]), "+f"(c[3])
        : "r"(a[0]), "r"(a[1]), "r"(a[2]), "r"(a[3]), "r"(b[0]), "r"(b[1]));
}

// ---------------------------------------------------------------------------
// 1) convert fp32 -> fp16 (block per row); W blocks also reduce sigma
// ---------------------------------------------------------------------------
__global__ __launch_bounds__(128) void prep_kernel(const float* __restrict__ W,
                                                   const float* __restrict__ X) {
    __shared__ float s_w2[4];
    const int bid = blockIdx.x;
    const int tid = threadIdx.x;

    if (bid < M_OUT) {
        const float4 v = ((const float4*)(W + (size_t)bid * K_IN))[tid];
        __half2* dst = (__half2*)(g_Wh + (size_t)bid * K_IN);
        dst[2 * tid]     = __floats2half2_rn(v.x, v.y);
        dst[2 * tid + 1] = __floats2half2_rn(v.z, v.w);
        float w2 = v.x * v.x + v.y * v.y + v.z * v.z + v.w * v.w;
#pragma unroll
        for (int off = 16; off; off >>= 1)
            w2 += __shfl_xor_sync(0xffffffffu, w2, off);
        if ((tid & 31) == 0) s_w2[tid >> 5] = w2;
        __syncthreads();
        if (tid == 0)
            g_sig[bid] = sqrtf(s_w2[0] + s_w2[1] + s_w2[2] + s_w2[3]);
    } else {
        const int r = bid - M_OUT;
        const float4 v = ((const float4*)(X + (size_t)r * K_IN))[tid];
        __half2* dst = (__half2*)(g_Xh + (size_t)r * K_IN);
        dst[2 * tid]     = __floats2half2_rn(v.x, v.y);
        dst[2 * tid + 1] = __floats2half2_rn(v.z, v.w);
    }
}

// ---------------------------------------------------------------------------
// 2) HMMA GEMM: CTA 128x128, warp 64x32, BK=64, 2-stage, 2 CTAs/SM
// ---------------------------------------------------------------------------
__global__ __launch_bounds__(256, 2) void gemm_kernel(const float* __restrict__ bias) {
    extern __shared__ __align__(16) char smem[];
    const uint32_t sb = smem_u32(smem);

    const int tid = threadIdx.x;
    const int w = tid >> 5, lane = tid & 31;
    const int wm = w >> 2, wn = w & 3;
    const int g = lane >> 2, tg = lane & 3;
    const int m0 = blockIdx.y * TM, n0 = blockIdx.x * TN;

    const int rbase = tid >> 3;
    const uint32_t dOffBase = (uint32_t)(rbase * ROWB + (tid & 7) * 16);
    const __half* aSrcBase = g_Wh + (size_t)(m0 + rbase) * K_IN + (tid & 7) * 8;
    const __half* bSrcBase = g_Xh + (size_t)(n0 + rbase) * K_IN + (tid & 7) * 8;

#define ISSUE(st) do {                                                     \
        const uint32_t _ab = sb + ((st) & 1) * A_STG + dOffBase;           \
        const __half* _as = aSrcBase + (st) * BKK;                         \
        cpasync16(_ab,                 _as);                               \
        cpasync16(_ab + 1 * 32 * ROWB, _as + 1 * 32 * K_IN);               \
        cpasync16(_ab + 2 * 32 * ROWB, _as + 2 * 32 * K_IN);               \
        cpasync16(_ab + 3 * 32 * ROWB, _as + 3 * 32 * K_IN);               \
        const uint32_t _bb = sb + B_BASE + ((st) & 1) * B_STG + dOffBase;  \
        const __half* _bs = bSrcBase + (st) * BKK;                         \
        cpasync16(_bb,                 _bs);                               \
        cpasync16(_bb + 1 * 32 * ROWB, _bs + 1 * 32 * K_IN);               \
        cpasync16(_bb + 2 * 32 * ROWB, _bs + 2 * 32 * K_IN);               \
        cpasync16(_bb + 3 * 32 * ROWB, _bs + 3 * 32 * K_IN);               \
        CP_COMMIT();                                                       \
    } while (0)

    ISSUE(0);

    float acc[4][4][4];
#pragma unroll
    for (int i = 0; i < 4; i++)
#pragma unroll
        for (int j = 0; j < 4; j++)
#pragma unroll
            for (int r = 0; r < 4; r++) acc[i][j][r] = 0.f;

    const uint32_t aLane =
        (uint32_t)(wm * 64 + (lane & 15)) * ROWB + (uint32_t)(lane >> 4) * 16;
    const uint32_t bLane =
        (uint32_t)(wn * 32 + ((lane >> 4) * 8) + (lane & 7)) * ROWB +
        (uint32_t)((lane >> 3) & 1) * 16;

    for (int s = 0; s < NSTG; s++) {
        CP_WAIT(0);
        __syncthreads();
        if (s + 1 < NSTG) ISSUE(s + 1);
        const int bufi = s & 1;
        const uint32_t aS = sb + bufi * A_STG + aLane;
        const uint32_t bS = sb + B_BASE + bufi * B_STG + bLane;
#pragma unroll
        for (int j = 0; j < 4; j++) {
            uint32_t a[4][4], b[4][2];
#pragma unroll
            for (int i = 0; i < 4; i++)
                ldsm4(aS + (uint32_t)(i * 16 * ROWB) + j * 32, a[i]);
#pragma unroll
            for (int jj = 0; jj < 2; jj++) {
                uint32_t r[4];
                ldsm4(bS + (uint32_t)(jj * 16 * ROWB) + j * 32, r);
                b[2 * jj][0] = r[0]; b[2 * jj][1] = r[1];
                b[2 * jj + 1][0] = r[2]; b[2 * jj + 1][1] = r[3];
            }
#pragma unroll
            for (int i = 0; i < 4; i++)
#pragma unroll
                for (int jn = 0; jn < 4; jn++) mma16816(acc[i][jn], a[i], b[jn]);
        }
    }
#undef ISSUE

#pragma unroll
    for (int i = 0; i < 4; i++) {
        const int o_lo = m0 + wm * 64 + i * 16 + g;
        const float b_lo = bias[o_lo];
        const float b_hi = bias[o_lo + 8];
#pragma unroll
        for (int jn = 0; jn < 4; jn++) {
            const int n = n0 + wn * 32 + jn * 8 + tg * 2;
            *(__half2*)(g_Lh + (size_t)o_lo * N_BATCH + n) =
                __floats2half2_rn(acc[i][jn][0] + b_lo, acc[i][jn][1] + b_lo);
            *(__half2*)(g_Lh + (size_t)(o_lo + 8) * N_BATCH + n) =
                __floats2half2_rn(acc[i][jn][2] + b_hi, acc[i][jn][3] + b_hi);
        }
    }
}

// ---------------------------------------------------------------------------
// 3) select: bucket-histogram + band classification + bitmask emission
//    (ballot+popc replaces per-thread counters and block reductions)
// ---------------------------------------------------------------------------
__global__ __launch_bounds__(256) void select_kernel(const float* __restrict__ bias) {
    __shared__ int hist[NB];
    __shared__ int sTop, sA, scnt;
    __shared__ float sThi, sTlo;
    __shared__ int sBad;

    const int tid = threadIdx.x;
    const int o = blockIdx.x;
    const int lane = tid & 31;
    const int wrp = tid >> 5;

    if (tid < NB) hist[tid] = 0;
    if (tid == 0) { sTop = 0; sA = 0; scnt = 0; sBad = 0; }
    __syncthreads();

    const float sigma = g_sig[o];
    const float stepv = ZSTEP * sigma;
    const float t0 = bias[o] + (ZC - ZHALF) * sigma;
    const float invstep = 1.0f / stepv;
    const float gridtop = t0 + (float)NB * stepv;

    const __half2* col = (const __half2*)(g_Lh + (size_t)o * N_BATCH);
    float v[16];
#pragma unroll
    for (int q = 0; q < 8; q++) {
        const float2 f = __half22float2(col[tid + 256 * q]);
        v[2 * q] = f.x;
        v[2 * q + 1] = f.y;
    }

    // pass 1: bucketize; count-above-grid via ballot+popc (lane 0 only)
    int top = 0;
#pragma unroll
    for (int q = 0; q < 16; q++) {
        const unsigned bt = __ballot_sync(0xffffffffu, v[q] >= gridtop);
        if (lane == 0) top += __popc(bt);
        const float f = (v[q] - t0) * invstep;
        if (f >= 0.f && f < (float)NB) atomicAdd(&hist[(int)f], 1);
    }
    if (lane == 0 && top) atomicAdd(&sTop, top);
    __syncthreads();

    if (tid == 0) {
        int run = sTop;
        int e = -1;
        if (run >= K_SEL) {
            sBad = 1;
        } else {
            for (int i = NB - 1; i >= 0; i--) {
                run += hist[i];
                if (run >= K_SEL) { e = i; break; }
            }
            if (e < 0) sBad = 1;
        }
        if (e >= 0) {
            sThi = t0 + (float)(e + 1) * stepv + DELTA * sigma;
            sTlo = t0 + (float)e * stepv - DELTA * sigma;
        }
    }
    __syncthreads();
    if (sBad) {
        if (tid == 0) g_ucnt[o] = CAP + 1;
        return;
    }
    const float T_hi = sThi, T_lo = sTlo;

    // pass 2: bitmask + certain-count via popc + band gather
    int a = 0;
#pragma unroll
    for (int p = 0; p < 8; p++) {
        const float x0 = v[2 * p], x1 = v[2 * p + 1];
        const unsigned ev = __ballot_sync(0xffffffffu, x0 > T_hi);
        const unsigned od = __ballot_sync(0xffffffffu, x1 > T_hi);
        if (lane == 0) {
            const int cid = 8 * p + wrp;
            g_bits[(size_t)o * 128 + 2 * cid]     = ev;
            g_bits[(size_t)o * 128 + 2 * cid + 1] = od;
            a += __popc(ev) + __popc(od);
        }
        if (x0 <= T_hi && x0 > T_lo) {
            const int pp = atomicAdd(&scnt, 1);
            if (pp < CAP) g_uidx[(size_t)o * CAP + pp] = 2 * tid + 512 * p;
        }
        if (x1 <= T_hi && x1 > T_lo) {
            const int pp = atomicAdd(&scnt, 1);
            if (pp < CAP) g_uidx[(size_t)o * CAP + pp] = 2 * tid + 512 * p + 1;
        }
    }
    if (lane == 0 && a) atomicAdd(&sA, a);
    __syncthreads();
    if (tid == 0) {
        if (scnt > CAP) {
            g_ucnt[o] = CAP + 1;
        } else {
            g_ucnt[o] = scnt;
            g_r[o] = K_SEL - sA;
        }
    }
}

// ---------------------------------------------------------------------------
// 4) mask: expand bitmask -> fp32; 128(b) x 32(o) tiles, float4 stores
// ---------------------------------------------------------------------------
__global__ __launch_bounds__(256) void mask_kernel(float* __restrict__ out) {
    __shared__ unsigned sbits[32][4];
    const int tx = threadIdx.x, ty = threadIdx.y;
    const int tid = ty * 32 + tx;
    const int b0 = blockIdx.x * 128, o0 = blockIdx.y * 32;

    if (tid < 128) {
        const int ol = tid >> 2, wi = tid & 3;
        sbits[ol][wi] = g_bits[(size_t)(o0 + ol) * 128 + (b0 >> 6) * 2 + wi];
    }
    __syncthreads();

    const int j = tx & 7;
    const int bg = tx >> 3;
#pragma unroll
    for (int i = 0; i < 4; i++) {
        const int b = ty * 16 + i * 4 + bg;
        const int c = b >> 6;
        const int idx = b & 63;
        const int sh = idx >> 1;
        const int par = idx & 1;
        float4 v;
#pragma unroll
        for (int k = 0; k < 4; k++) {
            const unsigned word = sbits[4 * j + k][2 * c + par];
            ((float*)&v)[k] = ((word >> sh) & 1u) ? 1.0f : 0.0f;
        }
        *(float4*)(out + (size_t)(b0 + b) * M_OUT + o0 + 4 * j) = v;
    }
}

// ---------------------------------------------------------------------------
// 5) repair: exact fp32 ascending-k chain; parallel rank selection
// ---------------------------------------------------------------------------
__global__ __launch_bounds__(128) void repair_kernel(const float* __restrict__ W,
                                                     const float* __restrict__ X,
                                                     const float* __restrict__ bias,
                                                     float* __restrict__ out) {
    const int o = blockIdx.x;
    const int tid = threadIdx.x;
    const int c = g_ucnt[o];
    if (c == 0) return;

    const float4* wr4 = (const float4*)(W + (size_t)o * K_IN);

    if (c <= CAP) {
        __shared__ float vals[CAP];
        __shared__ int idxs[CAP];
        if (tid < c) {
            const int b = g_uidx[(size_t)o * CAP + tid];
            const float4* xr4 = (const float4*)(X + (size_t)b * K_IN);
            float acc = 0.f;
            for (int k = 0; k < K_IN / 4; k++) {
                const float4 wv = wr4[k], xv = xr4[k];
                acc = __fmaf_rn(wv.x, xv.x, acc);
                acc = __fmaf_rn(wv.y, xv.y, acc);
                acc = __fmaf_rn(wv.z, xv.z, acc);
                acc = __fmaf_rn(wv.w, xv.w, acc);
            }
            vals[tid] = acc + bias[o];
            idxs[tid] = b;
        }
        __syncthreads();
        if (tid < c) {
            const int r = g_r[o];
            const float v = vals[tid];
            const int ib = idxs[tid];
            int rank = 0;
            for (int jj = 0; jj < c; jj++) {
                const float vj = vals[jj];
                rank += (vj > v || (vj == v && idxs[jj] < ib)) ? 1 : 0;
            }
            if (rank < r) out[(size_t)ib * M_OUT + o] = 1.0f;
        }
        return;
    }

    // fallback: recompute whole column exactly + exact radix select with ties
    __shared__ unsigned keys[N_BATCH];
    __shared__ unsigned hist[256];
    __shared__ unsigned s_prefix;
    __shared__ int s_rem, s_cut;
    for (int b = tid; b < N_BATCH; b += 128) {
        const float4* xr4 = (const float4*)(X + (size_t)b * K_IN);
        float acc = 0.f;
        for (int k = 0; k < K_IN / 4; k++) {
            const float4 wv = wr4[k], xv = xr4[k];
            acc = __fmaf_rn(wv.x, xv.x, acc);
            acc = __fmaf_rn(wv.y, xv.y, acc);
            acc = __fmaf_rn(wv.z, xv.z, acc);
            acc = __fmaf_rn(wv.w, xv.w, acc);
        }
        const float f = acc + bias[o];
        const unsigned u = __float_as_uint(f);
        keys[b] = u ^ ((u & 0x80000000u) ? 0xFFFFFFFFu : 0x80000000u);
    }
    if (tid == 0) { s_prefix = 0u; s_rem = K_SEL; }
    const unsigned himasks[4] = {0u, 0xFF000000u, 0xFFFF0000u, 0xFFFFFF00u};
#pragma unroll
    for (int pass = 0; pass < 4; pass++) {
        const int shift = 24 - 8 * pass;
        __syncthreads();
        hist[tid] = 0;
        hist[tid + 128] = 0;
        __syncthreads();
        const unsigned hm = himasks[pass];
        const unsigned pfx = s_prefix;
        for (int i = tid; i < N_BATCH; i += 128) {
            const unsigned u = keys[i];
            if ((u & hm) == (pfx & hm)) atomicAdd(&hist[(u >> shift) & 255], 1u);
        }
        __syncthreads();
        if (tid == 0) {
            unsigned cum = 0;
            int d;
            for (d = 255; d >= 0; d--) {
                cum += hist[d];
                if ((int)cum >= s_rem) break;
            }
            s_rem -= (int)(cum - hist[d]);
            s_prefix = pfx | ((unsigned)d << shift);
        }
    }
    __syncthreads();
    const unsigned tau = s_prefix;
    const int rem = s_rem;
    const int base = tid * 32;
    int cnt = 0;
#pragma unroll
    for (int j = 0; j < 32; j++) cnt += (keys[base + j] == tau) ? 1 : 0;
    __syncthreads();
    hist[tid] = (unsigned)cnt;
    __syncthreads();
    for (int off = 1; off < 128; off <<= 1) {
        const unsigned v = hist[tid];
        const unsigned a = (tid >= off) ? hist[tid - off] : 0u;
        __syncthreads();
        hist[tid] = v + a;
        __syncthreads();
    }
    const int incl = (int)hist[tid];
    const int excl = incl - cnt;
    if (excl < rem && rem <= incl) {
        int need = rem - excl;
        for (int j = 0; j < 32; j++) {
            if (keys[base + j] == tau && --need == 0) { s_cut = base + j; break; }
        }
    }
    __syncthreads();
    const int cut = s_cut;
    for (int b = tid; b < N_BATCH; b += 128) {
        const unsigned k = keys[b];
        out[(size_t)b * M_OUT + o] = (k > tau || (k == tau && b <= cut)) ? 1.0f : 0.0f;
    }
}

// ---------------------------------------------------------------------------
extern "C" void kernel_launch(void* const* d_in, const int* in_sizes, int n_in,
                              void* d_out, int out_size) {
    const float* x = (const float*)d_in[0];  // [4096, 512]
    const float* W = (const float*)d_in[1];  // [8192, 512]
    const float* b = (const float*)d_in[2];  // [8192]
    float* out = (float*)d_out;              // [4096, 8192]

    cudaFuncSetAttribute(gemm_kernel,
                         cudaFuncAttributeMaxDynamicSharedMemorySize, SMEM_GEMM);

    prep_kernel<<<M_OUT + N_BATCH, 128>>>(W, x);
    gemm_kernel<<<dim3(N_BATCH / TN, M_OUT / TM), 256, SMEM_GEMM>>>(b);
    select_kernel<<<M_OUT, 256>>>(b);
    mask_kernel<<<dim3(N_BATCH / 128, M_OUT / 32), dim3(32, 8)>>>(out);  // 4th: profiled
    repair_kernel<<<M_OUT, 128>>>(W, x, b, out);
}